// round 14
// baseline (speedup 1.0000x reference)
#include <cuda_runtime.h>
#include <cuda_bf16.h>
#include <cstdint>

#define NN 50000
#define NE 600000
#define NG 500
#define HID 128
#define NL 3
#define NC 10
#define NBLK 49        // scan blocks: ceil(50000/1024)

typedef unsigned long long u64;

// ---------------- scratch ----------------
__device__ float g_x1[NN * HID];
__device__ float g_x2[NN * HID];
__device__ int   g_deg[NN];
__device__ int   g_off[NN + 1];
__device__ int   g_cur[NN];
__device__ int   g_srcs[NE];
__device__ int   g_gcnt[NG];
__device__ int   g_goff[NG + 1];
__device__ int   g_bsum[NBLK];
__device__ int   g_bbase[NBLK];

// ---------------- PTX helpers (plain sm_80+; nothing 'a'-gated) ----------------
__device__ __forceinline__ uint32_t smem_u32(const void* p) {
    uint32_t a;
    asm("{ .reg .u64 t; cvta.to.shared.u64 t, %1; cvt.u32.u64 %0, t; }" : "=r"(a) : "l"(p));
    return a;
}
__device__ __forceinline__ void ldsm4(uint32_t* r, uint32_t addr) {
    asm volatile("ldmatrix.sync.aligned.m8n8.x4.shared.b16 {%0,%1,%2,%3}, [%4];"
                 : "=r"(r[0]), "=r"(r[1]), "=r"(r[2]), "=r"(r[3]) : "r"(addr));
}
__device__ __forceinline__ void mma16816(float* c, const uint32_t* a, uint32_t b0, uint32_t b1) {
    asm volatile("mma.sync.aligned.m16n8k16.row.col.f32.bf16.bf16.f32 "
                 "{%0,%1,%2,%3}, {%4,%5,%6,%7}, {%8,%9}, {%0,%1,%2,%3};"
                 : "+f"(c[0]), "+f"(c[1]), "+f"(c[2]), "+f"(c[3])
                 : "r"(a[0]), "r"(a[1]), "r"(a[2]), "r"(a[3]), "r"(b0), "r"(b1));
}

// smem layout (bytes).  A half-tile: 128 rows x 136 bf16 (272B stride, pad 8 -> LDSM conflict-free).
// B: 128 j x 264 bf16 (528B stride, K=256 + pad 8).
#define S_BIAS 0
#define S_AH   512
#define S_AL   (S_AH + 128 * 272)
#define S_BH   (S_AL + 128 * 272)
#define S_BL   (S_BH + 128 * 528)
#define S_TOTAL (S_BL + 128 * 528)   // 205312 bytes

// ---------------- CSR build ----------------
__global__ void zero_kernel() {
    int i = blockIdx.x * blockDim.x + threadIdx.x;
    if (i < NN) g_deg[i] = 0;
    if (i < NG) g_gcnt[i] = 0;
}

__global__ void count_kernel(const int* __restrict__ ei, const int* __restrict__ batch) {
    int e = blockIdx.x * blockDim.x + threadIdx.x;
    if (e < NE) atomicAdd(&g_deg[ei[NE + e]], 1);
    if (e < NN) atomicAdd(&g_gcnt[batch[e]], 1);
}

__global__ void scan1_kernel() {
    __shared__ int wsum[32];
    int tid = threadIdx.x, lane = tid & 31, w = tid >> 5;
    int i = blockIdx.x * 1024 + tid;
    int v = (i < NN) ? g_deg[i] : 0;
    int xs = v;
#pragma unroll
    for (int o = 1; o < 32; o <<= 1) {
        int t = __shfl_up_sync(0xffffffffu, xs, o);
        if (lane >= o) xs += t;
    }
    if (lane == 31) wsum[w] = xs;
    __syncthreads();
    if (w == 0) {
        int s = wsum[lane];
#pragma unroll
        for (int o = 1; o < 32; o <<= 1) {
            int t = __shfl_up_sync(0xffffffffu, s, o);
            if (lane >= o) s += t;
        }
        wsum[lane] = s;
    }
    __syncthreads();
    int base = (w > 0) ? wsum[w - 1] : 0;
    int incl = xs + base;
    if (i < NN) g_off[i] = incl - v;
    if (tid == 1023) g_bsum[blockIdx.x] = incl;
}

__global__ void scan2_kernel() {
    __shared__ int bs[NBLK];
    __shared__ int gs[512];
    int tid = threadIdx.x;
    if (tid < NBLK) bs[tid] = g_bsum[tid];
    int gv = (tid < NG) ? g_gcnt[tid] : 0;
    gs[tid] = gv;
    __syncthreads();
    if (tid == 0) {
        int r = 0;
        for (int i = 0; i < NBLK; i++) { int t = bs[i]; bs[i] = r; r += t; }
        g_off[NN] = r;
    }
    for (int o = 1; o < 512; o <<= 1) {
        int t = (tid >= o) ? gs[tid - o] : 0;
        __syncthreads();
        gs[tid] += t;
        __syncthreads();
    }
    if (tid < NG) g_goff[tid] = gs[tid] - gv;
    if (tid == NG - 1) g_goff[NG] = gs[tid];
    if (tid < NBLK) g_bbase[tid] = bs[tid];
}

__global__ void scan3_kernel() {
    int i = blockIdx.x * 1024 + threadIdx.x;
    if (i >= NN) return;
    int v = g_off[i] + g_bbase[blockIdx.x];
    g_off[i] = v;
    g_cur[i] = v;
}

__global__ void bucket_kernel(const int* __restrict__ ei) {
    int e = blockIdx.x * blockDim.x + threadIdx.x;
    if (e >= NE) return;
    int src = ei[e];
    int dst = ei[NE + e];
    int pos = atomicAdd(&g_cur[dst], 1);
    g_srcs[pos] = src;
}

// -------- hi/lo bf16 split of a float4 -> two u64 (4 bf16 each) --------
__device__ __forceinline__ void split4(float4 v, u64& hi, u64& lo) {
    __nv_bfloat162 h01 = __floats2bfloat162_rn(v.x, v.y);
    __nv_bfloat162 h23 = __floats2bfloat162_rn(v.z, v.w);
    float rx = v.x - __bfloat162float(__low2bfloat16(h01));
    float ry = v.y - __bfloat162float(__high2bfloat16(h01));
    float rz = v.z - __bfloat162float(__low2bfloat16(h23));
    float rw = v.w - __bfloat162float(__high2bfloat16(h23));
    __nv_bfloat162 l01 = __floats2bfloat162_rn(rx, ry);
    __nv_bfloat162 l23 = __floats2bfloat162_rn(rz, rw);
    uint32_t a = *reinterpret_cast<uint32_t*>(&h01);
    uint32_t b = *reinterpret_cast<uint32_t*>(&h23);
    uint32_t c = *reinterpret_cast<uint32_t*>(&l01);
    uint32_t d = *reinterpret_cast<uint32_t*>(&l23);
    hi = (u64)a | ((u64)b << 32);
    lo = (u64)c | ((u64)d << 32);
}

// ---------------- fused SAGE layer: CSR mean-gather + HMMA GEMM ----------------
// D[128 nodes][128 j] = [mean|x](K=256, hi/lo bf16) @ [Wl|Wr]^T ; relu(D + bl) -> out
// 8 warps: warp = (row-group 0..3: 32 rows) x (col-group 0..1: 64 j) for MMA;
// for the mean-gather, warp w owns tile rows w*16..w*16+15 (lane = float4 chunk).
__global__ void __launch_bounds__(256, 1)
fused_layer_kernel(const float* __restrict__ xin,
                   const float* __restrict__ Wl, const float* __restrict__ bl,
                   const float* __restrict__ Wr, float* __restrict__ out)
{
    extern __shared__ __align__(16) char smem[];
    const uint32_t sb32 = smem_u32(smem);
    const int tid = threadIdx.x;
    const int wid = tid >> 5;
    const int lane = tid & 31;
    const int g = lane >> 2, tg = lane & 3;
    const int rowbase = (wid & 3) * 32;
    const int colbase = (wid >> 2) * 64;
    float* bias = reinterpret_cast<float*>(smem + S_BIAS);
    const float4* x4p = reinterpret_cast<const float4*>(xin);

    // ---- stage weights (hi/lo) once: B[j][k], j row stride 264 bf16 (528B) ----
    for (int idx = tid; idx < 2 * 128 * 32; idx += 256) {
        int mat = idx >> 12;                 // 0=Wl (k 0..127), 1=Wr (k 128..255)
        int rem = idx & 4095;
        int r = rem >> 5, kg = rem & 31;
        const float* W = mat ? Wr : Wl;
        float4 v = __ldg(reinterpret_cast<const float4*>(&W[r * HID + kg * 4]));
        u64 hi, lo;
        split4(v, hi, lo);
        uint32_t off = (uint32_t)(r * 528 + mat * 256 + kg * 8);
        *reinterpret_cast<u64*>(smem + S_BH + off) = hi;
        *reinterpret_cast<u64*>(smem + S_BL + off) = lo;
    }
    if (tid < HID) bias[tid] = bl[tid];
    __syncthreads();

    // per-lane ldmatrix base offsets
    const uint32_t laneA = (uint32_t)((lane & 15) * 272 + ((lane >> 4) & 1) * 16);
    const uint32_t laneB = (uint32_t)((colbase + (lane & 7) + ((lane >> 4) & 1) * 8) * 528
                                      + ((lane >> 3) & 1) * 16);

    const int NT = (NN + 127) / 128;         // 391
    for (int tile = blockIdx.x; tile < NT; tile += gridDim.x) {
        const int base = tile * 128;
        float acc[2][8][4];
#pragma unroll
        for (int mb = 0; mb < 2; mb++)
#pragma unroll
            for (int nt = 0; nt < 8; nt++)
#pragma unroll
                for (int q = 0; q < 4; q++) acc[mb][nt][q] = 0.f;

#pragma unroll
        for (int half = 0; half < 2; half++) {
            if (half == 0) {
                // ---- fused mean-gather directly into A smem (hi/lo) ----
                // warp wid owns rows wid*16 .. wid*16+15; lane = float4 feature chunk
                for (int i = 0; i < 16; i++) {
                    int r = wid * 16 + i;
                    int n = base + r; if (n >= NN) n = NN - 1;
                    int s0 = g_off[n], s1 = g_off[n + 1];
                    float4 a = make_float4(0.f, 0.f, 0.f, 0.f);
                    int e = s0;
                    for (; e + 4 <= s1; e += 4) {
                        int i0 = __ldg(&g_srcs[e]);
                        int i1 = __ldg(&g_srcs[e + 1]);
                        int i2 = __ldg(&g_srcs[e + 2]);
                        int i3 = __ldg(&g_srcs[e + 3]);
                        float4 v0 = __ldg(&x4p[(long)i0 * 32 + lane]);
                        float4 v1 = __ldg(&x4p[(long)i1 * 32 + lane]);
                        float4 v2 = __ldg(&x4p[(long)i2 * 32 + lane]);
                        float4 v3 = __ldg(&x4p[(long)i3 * 32 + lane]);
                        a.x += (v0.x + v1.x) + (v2.x + v3.x);
                        a.y += (v0.y + v1.y) + (v2.y + v3.y);
                        a.z += (v0.z + v1.z) + (v2.z + v3.z);
                        a.w += (v0.w + v1.w) + (v2.w + v3.w);
                    }
                    for (; e < s1; e++) {
                        int s = __ldg(&g_srcs[e]);
                        float4 v = __ldg(&x4p[(long)s * 32 + lane]);
                        a.x += v.x; a.y += v.y; a.z += v.z; a.w += v.w;
                    }
                    float inv = 1.f / (float)max(s1 - s0, 1);
                    float4 v = make_float4(a.x * inv, a.y * inv, a.z * inv, a.w * inv);
                    u64 hi, lo;
                    split4(v, hi, lo);
                    uint32_t off = (uint32_t)(r * 272 + lane * 8);
                    *reinterpret_cast<u64*>(smem + S_AH + off) = hi;
                    *reinterpret_cast<u64*>(smem + S_AL + off) = lo;
                }
            } else {
                // ---- stage x half (hi/lo): linear row reads ----
                for (int idx = tid; idx < 128 * 32; idx += 256) {
                    int r = idx >> 5, kg = idx & 31;
                    int n = base + r; if (n >= NN) n = NN - 1;
                    float4 v = __ldg(reinterpret_cast<const float4*>(&xin[(long)n * HID + kg * 4]));
                    u64 hi, lo;
                    split4(v, hi, lo);
                    uint32_t off = (uint32_t)(r * 272 + kg * 8);
                    *reinterpret_cast<u64*>(smem + S_AH + off) = hi;
                    *reinterpret_cast<u64*>(smem + S_AL + off) = lo;
                }
            }
            __syncthreads();

            const uint32_t kbyte = (uint32_t)(half * 256);   // B col byte offset (128 bf16)
#pragma unroll
            for (int term = 0; term < 3; term++) {
                uint32_t Ab = sb32 + (term == 2 ? S_AL : S_AH) + rowbase * 272 + laneA;
                uint32_t Bb = sb32 + (term == 1 ? S_BL : S_BH) + laneB + kbyte;
#pragma unroll
                for (int ks = 0; ks < 8; ks++) {
                    uint32_t aF[2][4];
                    ldsm4(aF[0], Ab + ks * 32);
                    ldsm4(aF[1], Ab + 16 * 272 + ks * 32);
                    uint32_t bF[4][4];
#pragma unroll
                    for (int np = 0; np < 4; np++)
                        ldsm4(bF[np], Bb + np * 16 * 528 + ks * 32);
#pragma unroll
                    for (int mb = 0; mb < 2; mb++)
#pragma unroll
                        for (int np = 0; np < 4; np++) {
                            mma16816(acc[mb][np * 2 + 0], aF[mb], bF[np][0], bF[np][1]);
                            mma16816(acc[mb][np * 2 + 1], aF[mb], bF[np][2], bF[np][3]);
                        }
                }
            }
            __syncthreads();   // A smem free before restage / next tile
        }

        // ---- epilogue: bias + relu, float2 stores ----
#pragma unroll
        for (int mb = 0; mb < 2; mb++) {
            int r0 = base + rowbase + mb * 16 + g;
            int r1 = r0 + 8;
#pragma unroll
            for (int nt = 0; nt < 8; nt++) {
                int col = colbase + nt * 8 + 2 * tg;
                float2 bv = *reinterpret_cast<const float2*>(&bias[col]);
                float* c = acc[mb][nt];
                if (r0 < NN) {
                    float2 o = make_float2(fmaxf(c[0] + bv.x, 0.f), fmaxf(c[1] + bv.y, 0.f));
                    *reinterpret_cast<float2*>(&out[(long)r0 * HID + col]) = o;
                }
                if (r1 < NN) {
                    float2 o = make_float2(fmaxf(c[2] + bv.x, 0.f), fmaxf(c[3] + bv.y, 0.f));
                    *reinterpret_cast<float2*>(&out[(long)r1 * HID + col]) = o;
                }
            }
        }
    }
}

// ---------------- fused tail: pool + relu + mlp1 + mlp2 + log_softmax ----------------
__global__ void tail_kernel(const float* __restrict__ xf,
                            const float* __restrict__ W1, const float* __restrict__ b1,
                            const float* __restrict__ W2, const float* __restrict__ b2,
                            float* __restrict__ out) {
    int g = blockIdx.x;
    int j = threadIdx.x;
    __shared__ float sg[HID];
    __shared__ float sh[HID];
    __shared__ float slog[NC];

    int n0 = g_goff[g], n1 = g_goff[g + 1];
    float acc = 0.f;
    int n = n0;
    for (; n + 4 <= n1; n += 4) {
        float v0 = xf[(long)(n + 0) * HID + j];
        float v1 = xf[(long)(n + 1) * HID + j];
        float v2 = xf[(long)(n + 2) * HID + j];
        float v3 = xf[(long)(n + 3) * HID + j];
        acc += (v0 + v1) + (v2 + v3);
    }
    for (; n < n1; n++) acc += xf[(long)n * HID + j];
    sg[j] = fmaxf(acc, 0.f);
    __syncthreads();

    float a = b1[j];
    const float* wrow = &W1[j * HID];
#pragma unroll 8
    for (int k = 0; k < HID; k++) a += sg[k] * wrow[k];
    sh[j] = fmaxf(a, 0.f);
    __syncthreads();

    int w = j >> 5, lane = j & 31;
    for (int c = w; c < NC; c += 4) {
        float s = 0.f;
        for (int k = lane; k < HID; k += 32) s += sh[k] * W2[c * HID + k];
#pragma unroll
        for (int o = 16; o; o >>= 1) s += __shfl_down_sync(0xffffffffu, s, o);
        if (lane == 0) slog[c] = s + b2[c];
    }
    __syncthreads();

    if (j < NC) {
        float mx = -1e30f;
#pragma unroll
        for (int c = 0; c < NC; c++) mx = fmaxf(mx, slog[c]);
        float se = 0.f;
#pragma unroll
        for (int c = 0; c < NC; c++) se += expf(slog[c] - mx);
        out[g * NC + j] = slog[j] - mx - logf(se);
    }
}

// ---------------- launch ----------------
extern "C" void kernel_launch(void* const* d_in, const int* in_sizes, int n_in,
                              void* d_out, int out_size) {
    const float* x     = (const float*)d_in[0];
    const int*   ei    = (const int*)d_in[2];
    const int*   batch = (const int*)d_in[3];
    const float* Wl    = (const float*)d_in[4];
    const float* bl    = (const float*)d_in[5];
    const float* Wr    = (const float*)d_in[6];
    const float* W1    = (const float*)d_in[7];
    const float* b1    = (const float*)d_in[8];
    const float* W2    = (const float*)d_in[9];
    const float* b2    = (const float*)d_in[10];
    float* out = (float*)d_out;

    float *x1_p, *x2_p;
    cudaGetSymbolAddress((void**)&x1_p, g_x1);
    cudaGetSymbolAddress((void**)&x2_p, g_x2);

    cudaFuncSetAttribute(fused_layer_kernel, cudaFuncAttributeMaxDynamicSharedMemorySize, S_TOTAL);

    zero_kernel<<<(NN + 255) / 256, 256>>>();
    count_kernel<<<(NE + 255) / 256, 256>>>(ei, batch);
    scan1_kernel<<<NBLK, 1024>>>();
    scan2_kernel<<<1, 512>>>();
    scan3_kernel<<<NBLK, 1024>>>();
    bucket_kernel<<<(NE + 255) / 256, 256>>>(ei);

    const float* cur = x;
    float* nxt = x1_p;
    for (int l = 0; l < NL; l++) {
        fused_layer_kernel<<<148, 256, S_TOTAL>>>(cur,
                                                  Wl + l * HID * HID, bl + l * HID,
                                                  Wr + l * HID * HID, nxt);
        cur = nxt;
        nxt = (cur == x1_p) ? x2_p : x1_p;
    }

    tail_kernel<<<NG, HID>>>(cur, W1, b1, W2, b2, out);
}